// round 8
// baseline (speedup 1.0000x reference)
#include <cuda_runtime.h>
#include <cstdint>

// Fixed problem geometry: H=W=2048, step=2 -> nu=nv=1024, N=2^20 nodes.
constexpr int NU = 1024;
constexpr int NV = 1024;
constexpr int N  = NU * NV;
constexpr int W  = 2048;

// Output layout (floats): pts[3N] nrm[3N] radii[N] lens[4N] areas[2N]
constexpr int OFF_PTS  = 0;
constexpr int OFF_NRM  = 3 * N;
constexpr int OFF_RAD  = 6 * N;
constexpr int OFF_LEN  = 7 * N;
constexpr int OFF_AREA = 11 * N;

// Fast sqrt: MUFU.RSQ + FMUL; x==0 -> 0 (guard avoids NaN).
__device__ __forceinline__ float fast_sqrt(float x) {
    return x * rsqrtf(fmaxf(x, 1e-30f));
}

struct F3 { float x, y, z; };

__device__ __forceinline__ F3 loadA(const float* __restrict__ p, int jv, int iu) {
    // anchor (iu, jv): float offset = (2jv*W + 2iu)*3 (int32-safe, 8B aligned)
    int off = jv * (6 * W) + iu * 6;
    float2 ab = *reinterpret_cast<const float2*>(p + off);
    F3 r; r.x = ab.x; r.y = ab.y; r.z = p[off + 2];
    return r;
}

__device__ __forceinline__ float dist3(const F3& a, const F3& b) {
    float dx = a.x - b.x, dy = a.y - b.y, dz = a.z - b.z;
    return fast_sqrt(dx * dx + dy * dy + dz * dz);
}

// ---------------------------------------------------------------------------
// K1: forward pass. 1 node/thread, no smem. Own 2x2 point window via LDG
// (neighbor loads are L1 hits). Writes pts, nrm, lens (masked 0), areas.
// ---------------------------------------------------------------------------
__global__ __launch_bounds__(256)
void k_fwd(const float* __restrict__ cand,
           const float* __restrict__ cnrm,
           float* __restrict__ out) {
    int k  = blockIdx.x * 256 + threadIdx.x;
    int iu = k & (NU - 1);
    int jv = k >> 10;
    bool re = iu < NU - 1;
    bool de = jv < NV - 1;
    bool rd = re && de;
    int iuR = re ? iu + 1 : iu;
    int jvD = de ? jv + 1 : jv;

    F3 P0 = loadA(cand, jv,  iu);
    F3 PR = loadA(cand, jv,  iuR);
    F3 PD = loadA(cand, jvD, iu);
    F3 PG = loadA(cand, jvD, iuR);
    F3 NR = loadA(cnrm, jv,  iu);

    float dR = dist3(P0, PR);
    float dG = dist3(P0, PG);
    float dD = dist3(P0, PD);
    float dA = dist3(PR, PD);

    // areas
    float e1x = PR.x - P0.x, e1y = PR.y - P0.y, e1z = PR.z - P0.z;
    float e2x = PG.x - P0.x, e2y = PG.y - P0.y, e2z = PG.z - P0.z;
    float f2x = PD.x - P0.x, f2y = PD.y - P0.y, f2z = PD.z - P0.z;
    float cx = e1y * e2z - e1z * e2y;
    float cy = e1z * e2x - e1x * e2z;
    float cz = e1x * e2y - e1y * e2x;
    float gx = e2y * f2z - e2z * f2y;
    float gy = e2z * f2x - e2x * f2z;
    float gz = e2x * f2y - e2y * f2x;
    float a0 = 0.5f * fast_sqrt(cx * cx + cy * cy + cz * cz + 1e-13f);
    float a1 = 0.5f * fast_sqrt(gx * gx + gy * gy + gz * gz + 1e-13f);

    int p3 = OFF_PTS + 3 * k;
    out[p3 + 0] = P0.x; out[p3 + 1] = P0.y; out[p3 + 2] = P0.z;
    int n3 = OFF_NRM + 3 * k;
    out[n3 + 0] = NR.x; out[n3 + 1] = NR.y; out[n3 + 2] = NR.z;

    out[OFF_LEN + 0 * N + k] = re ? dR : 0.0f;
    out[OFF_LEN + 1 * N + k] = rd ? dG : 0.0f;
    out[OFF_LEN + 2 * N + k] = de ? dD : 0.0f;
    out[OFF_LEN + 3 * N + k] = rd ? dA : 0.0f;
    out[OFF_AREA + 0 * N + k] = rd ? a0 : 0.0f;
    out[OFF_AREA + 1 * N + k] = rd ? a1 : 0.0f;
}

// ---------------------------------------------------------------------------
// K2: radii gather, 2 nodes/thread (k even, k+1). Because masked edges are
// stored as exact 0 in lens, all 8 incident contributions per node are summed
// UNCONDITIONALLY; predication is needed only for genuinely out-of-bounds
// addresses (k==0 row start, jv==0 up-row). The count uses flags.
//   node a = k:   R[k] G[k] D[k] + A[k-1] R[k-1] G[k-NU-1] D[k-NU] A[k-NU]
//   node b = k+1: R[k] D[k+1] A[k] + R[k+1] G[k+1] G[k-NU] D[k+1-NU] A[k+1-NU]
// ---------------------------------------------------------------------------
__global__ __launch_bounds__(256)
void k_radii2(const float* __restrict__ lens, float* __restrict__ rad) {
    int i = blockIdx.x * 256 + threadIdx.x;   // pair index
    int k = 2 * i;                            // even node
    int iu = k & (NU - 1);
    int jv = k >> 10;
    bool ue  = jv > 0;
    bool de  = jv < NV - 1;
    bool le  = iu > 0;
    bool reb = iu < NU - 2;                   // node b has a right neighbor

    const float* L0 = lens;                   // right
    const float* L1 = lens + N;               // diag
    const float* L2 = lens + 2 * N;           // down
    const float* L3 = lens + 3 * N;           // anti

    float2 R = *reinterpret_cast<const float2*>(L0 + k);
    float2 G = *reinterpret_cast<const float2*>(L1 + k);
    float2 D = *reinterpret_cast<const float2*>(L2 + k);
    float  A0 = L3[k];

    float Rm1 = (k > 0)  ? L0[k - 1]      : 0.0f;
    float Am1 = (k > 0)  ? L3[k - 1]      : 0.0f;
    float Gul = (k > NU) ? L1[k - NU - 1] : 0.0f;
    float Gu  = ue ? L1[k - NU] : 0.0f;
    float2 Du = ue ? *reinterpret_cast<const float2*>(L2 + (k - NU)) : make_float2(0.0f, 0.0f);
    float2 Au = ue ? *reinterpret_cast<const float2*>(L3 + (k - NU)) : make_float2(0.0f, 0.0f);

    float suma = R.x + G.x + D.x + Am1 + Rm1 + Gul + Du.x + Au.x;
    float sumb = R.x + D.y + A0  + R.y + G.y + Gu  + Du.y + Au.y;

    float fde = de ? 1.0f : 0.0f;
    float fue = ue ? 1.0f : 0.0f;
    float base = 1.0f + 2.0f * fde + 2.0f * fue;
    float ext  = 1.0f + fde + fue;
    float cnta = base + (le  ? ext : 0.0f);
    float cntb = base + (reb ? ext : 0.0f);

    *reinterpret_cast<float2*>(rad + k) = make_float2(suma / cnta, sumb / cntb);
}

// ---------------------------------------------------------------------------
// Launch
// ---------------------------------------------------------------------------
extern "C" void kernel_launch(void* const* d_in, const int* in_sizes, int n_in,
                              void* d_out, int out_size) {
    (void)in_sizes; (void)n_in; (void)out_size;
    const float* cand = (const float*)d_in[1];
    const float* cnrm = (const float*)d_in[2];
    float* out = (float*)d_out;

    k_fwd<<<N / 256, 256>>>(cand, cnrm, out);
    k_radii2<<<(N / 2) / 256, 256>>>(out + OFF_LEN, out + OFF_RAD);
}

// round 10
// speedup vs baseline: 1.1412x; 1.1412x over previous
#include <cuda_runtime.h>
#include <cstdint>

// Fixed problem geometry: H=W=2048, step=2 -> nu=nv=1024, N=2^20 nodes.
constexpr int NU = 1024;
constexpr int NV = 1024;
constexpr int N  = NU * NV;
constexpr int W  = 2048;
constexpr int ROWF = 6 * W;        // floats per pixel row (12288)

// Output layout (floats): pts[3N] nrm[3N] radii[N] lens[4N] areas[2N]
constexpr int OFF_PTS  = 0;
constexpr int OFF_NRM  = 3 * N;
constexpr int OFF_RAD  = 6 * N;
constexpr int OFF_LEN  = 7 * N;
constexpr int OFF_AREA = 11 * N;

constexpr int TPB  = 256;          // threads per block
constexpr int COLS = 512;          // node columns per block (2 per thread)
// per-row smem: left halo @3, pair cols @6*t+6, right halo @3*COLS+6.
// SROW must be EVEN so every s[r] base is 8B-aligned (STS.64 legality).
constexpr int SROW = 3 * COLS + 10;   // 1546

__device__ __forceinline__ float fast_sqrt(float x) {
    return x * rsqrtf(fmaxf(x, 1e-30f));   // x==0 -> 0, not NaN
}

struct F3 { float x, y, z; };

__device__ __forceinline__ float dist3(const F3& a, const F3& b) {
    float dx = a.x - b.x, dy = a.y - b.y, dz = a.z - b.z;
    return fast_sqrt(dx * dx + dy * dy + dz * dz);
}

__device__ __forceinline__ F3 sub3(const F3& a, const F3& b) {
    F3 r; r.x = a.x - b.x; r.y = a.y - b.y; r.z = a.z - b.z; return r;
}

__device__ __forceinline__ float cross_area(const F3& u, const F3& v) {
    float cx = u.y * v.z - u.z * v.y;
    float cy = u.z * v.x - u.x * v.z;
    float cz = u.x * v.y - u.y * v.x;
    return 0.5f * fast_sqrt(cx * cx + cy * cy + cz * cz + 1e-13f);
}

__device__ __forceinline__ void st2(float* __restrict__ p, int off, float a, float b) {
    *reinterpret_cast<float2*>(p + off) = make_float2(a, b);
}

__device__ __forceinline__ F3 lds3(const float* __restrict__ s, int idx) {
    F3 r; r.x = s[idx]; r.y = s[idx + 1]; r.z = s[idx + 2]; return r;
}

__device__ __forceinline__ F3 loadA(const float* __restrict__ p, int jv, int iu) {
    int off = jv * ROWF + iu * 6;
    float2 ab = *reinterpret_cast<const float2*>(p + off);
    F3 r; r.x = ab.x; r.y = ab.y; r.z = p[off + 2];
    return r;
}

// ---------------------------------------------------------------------------
// One block = 512 node columns of one grid row; thread owns pair (iu even,
// iu+1). 3-row anchor-point window in smem; own-pair points stay in regs.
// ---------------------------------------------------------------------------
__global__ __launch_bounds__(TPB)
void k_pairrow(const float* __restrict__ cand,
               const float* __restrict__ cnrm,
               float* __restrict__ out) {
    __shared__ float s[3][SROW];   // 0=U(jv-1) 1=C(jv) 2=D(jv+1)

    const int t   = threadIdx.x;
    const int iu0 = blockIdx.x * COLS;
    const int jv  = blockIdx.y;
    const int iu  = iu0 + 2 * t;            // node a column (even)
    const int k   = jv * NU + iu;

    const bool ue   = jv > 0;
    const bool de   = jv < NV - 1;
    const bool le_a = iu > 0;
    const bool re_b = iu < NU - 2;
    const int jvU = ue ? jv - 1 : jv;
    const int jvD = de ? jv + 1 : jv;

    // --- stage pair anchors of rows U, C, D (3 LDG.128 per row) ---
    F3 Ua, Ub, Ca, Cb, Da, Db;
    {
        const int si = 6 * t + 6;
        #pragma unroll
        for (int r = 0; r < 3; r++) {
            const int jr = (r == 0) ? jvU : (r == 1) ? jv : jvD;
            const float4* g = reinterpret_cast<const float4*>(cand + jr * ROWF + 6 * iu);
            float4 q0 = g[0], q1 = g[1];
            float  q2 = (cand + jr * ROWF + 6 * iu)[8];
            F3 A; A.x = q0.x; A.y = q0.y; A.z = q0.z;      // col iu (pixel 2iu)
            F3 B; B.x = q1.z; B.y = q1.w; B.z = q2;        // col iu+1 (pixel 2iu+2)
            if (r == 0)      { Ua = A; Ub = B; }
            else if (r == 1) { Ca = A; Cb = B; }
            else             { Da = A; Db = B; }
            st2(s[r], si + 0, A.x, A.y);
            st2(s[r], si + 2, A.z, B.x);
            st2(s[r], si + 4, B.y, B.z);
        }
    }
    // halo columns: t==0 -> left (iu0-1), t==1 -> right (iu0+COLS)
    if (t < 2) {
        int iuH = (t == 0) ? (iu0 - 1) : (iu0 + COLS);
        iuH = min(max(iuH, 0), NU - 1);     // clamp; flag-guarded use
        const int si = (t == 0) ? 3 : (3 * COLS + 6);
        #pragma unroll
        for (int r = 0; r < 3; r++) {
            const int jr = (r == 0) ? jvU : (r == 1) ? jv : jvD;
            F3 h = loadA(cand, jr, iuH);
            s[r][si + 0] = h.x; s[r][si + 1] = h.y; s[r][si + 2] = h.z;
        }
    }

    // normals of the pair (registers only)
    F3 Na, Nb;
    {
        const float4* g = reinterpret_cast<const float4*>(cnrm + jv * ROWF + 6 * iu);
        float4 q0 = g[0], q1 = g[1];
        float  q2 = (cnrm + jv * ROWF + 6 * iu)[8];
        Na.x = q0.x; Na.y = q0.y; Na.z = q0.z;
        Nb.x = q1.z; Nb.y = q1.w; Nb.z = q2;
    }

    __syncthreads();

    // left-neighbor dists (node a's incoming edges from col iu-1)
    const int li = 6 * t + 3;
    F3 Cl = lds3(s[1], li);
    F3 Dl = lds3(s[2], li);
    F3 Ul = lds3(s[0], li);
    float dLa  = dist3(Ca, Cl);   // R[k-1]
    float dALa = dist3(Ca, Dl);   // A[k-1]
    float dULa = dist3(Ca, Ul);   // G[k-NU-1]

    // right-neighbor dists (node b's edges toward col iu+2)
    const int ri = 6 * t + 12;
    F3 Cr = lds3(s[1], ri);
    F3 Dr = lds3(s[2], ri);
    F3 Ur = lds3(s[0], ri);
    float dRb  = dist3(Cb, Cr);   // R[k+1]
    float dGb  = dist3(Cb, Dr);   // G[k+1]
    float dAb  = dist3(Cr, Db);   // A[k+1]
    float dURb = dist3(Cb, Ur);   // A[k+1-NU]

    // own + up dists
    float dRa  = dist3(Ca, Cb);   // R[k]
    float dGa  = dist3(Ca, Db);   // G[k]
    float dDa  = dist3(Ca, Da);   // D[k]
    float dAa  = dist3(Cb, Da);   // A[k]
    float dDb  = dist3(Cb, Db);   // D[k+1]
    float dUa  = dist3(Ca, Ua);   // D[k-NU]
    float dAUa = dist3(Ca, Ub);   // A[k-NU]
    float dULb = dist3(Cb, Ua);   // G[k-NU]
    float dUb  = dist3(Cb, Ub);   // D[k+1-NU]

    // areas
    F3 e1 = sub3(Cb, Ca), e2 = sub3(Db, Ca), f2 = sub3(Da, Ca);
    float a0a = cross_area(e1, e2);
    float a1a = cross_area(e2, f2);
    F3 g1 = sub3(Cr, Cb), g2 = sub3(Dr, Cb), h2 = sub3(Db, Cb);
    float a0b = cross_area(g1, g2);
    float a1b = cross_area(g2, h2);

    // radii sums & counts
    float suma = dRa, cnta = 1.0f;
    if (de)   { suma += dGa + dDa;  cnta += 2.0f; }
    if (ue)   { suma += dUa + dAUa; cnta += 2.0f; }
    if (le_a) {
        suma += dLa; cnta += 1.0f;
        if (de) { suma += dALa; cnta += 1.0f; }
        if (ue) { suma += dULa; cnta += 1.0f; }
    }
    float sumb = dRa, cntb = 1.0f;
    if (de)   { sumb += dDb + dAa;  cntb += 2.0f; }
    if (ue)   { sumb += dULb + dUb; cntb += 2.0f; }
    if (re_b) {
        sumb += dRb; cntb += 1.0f;
        if (de) { sumb += dGb;  cntb += 1.0f; }
        if (ue) { sumb += dURb; cntb += 1.0f; }
    }

    // --- outputs (all float2; k even -> 8B aligned) ---
    const int p3 = OFF_PTS + 3 * k;
    st2(out, p3 + 0, Ca.x, Ca.y);
    st2(out, p3 + 2, Ca.z, Cb.x);
    st2(out, p3 + 4, Cb.y, Cb.z);
    const int n3 = OFF_NRM + 3 * k;
    st2(out, n3 + 0, Na.x, Na.y);
    st2(out, n3 + 2, Na.z, Nb.x);
    st2(out, n3 + 4, Nb.y, Nb.z);
    st2(out, OFF_RAD + k, __fdividef(suma, cnta), __fdividef(sumb, cntb));

    const bool rdb = re_b && de;
    st2(out, OFF_LEN + 0 * N + k, dRa,             re_b ? dRb : 0.0f);
    st2(out, OFF_LEN + 1 * N + k, de ? dGa : 0.0f, rdb ? dGb : 0.0f);
    st2(out, OFF_LEN + 2 * N + k, de ? dDa : 0.0f, de ? dDb : 0.0f);
    st2(out, OFF_LEN + 3 * N + k, de ? dAa : 0.0f, rdb ? dAb : 0.0f);
    st2(out, OFF_AREA + 0 * N + k, de ? a0a : 0.0f, rdb ? a0b : 0.0f);
    st2(out, OFF_AREA + 1 * N + k, de ? a1a : 0.0f, rdb ? a1b : 0.0f);
}

// ---------------------------------------------------------------------------
// Launch
// ---------------------------------------------------------------------------
extern "C" void kernel_launch(void* const* d_in, const int* in_sizes, int n_in,
                              void* d_out, int out_size) {
    (void)in_sizes; (void)n_in; (void)out_size;
    const float* cand = (const float*)d_in[1];
    const float* cnrm = (const float*)d_in[2];
    float* out = (float*)d_out;

    dim3 grid(NU / COLS, NV);   // (2, 1024)
    k_pairrow<<<grid, TPB>>>(cand, cnrm, out);
}

// round 11
// speedup vs baseline: 1.1928x; 1.0452x over previous
#include <cuda_runtime.h>
#include <cstdint>

// Fixed problem geometry: H=W=2048, step=2 -> nu=nv=1024, N=2^20 nodes.
constexpr int NU = 1024;
constexpr int NV = 1024;
constexpr int N  = NU * NV;
constexpr int W  = 2048;
constexpr int ROWF = 6 * W;        // floats per pixel row (12288)

// Output layout (floats): pts[3N] nrm[3N] radii[N] lens[4N] areas[2N]
constexpr int OFF_PTS  = 0;
constexpr int OFF_NRM  = 3 * N;
constexpr int OFF_RAD  = 6 * N;
constexpr int OFF_LEN  = 7 * N;
constexpr int OFF_AREA = 11 * N;

constexpr int TPB = 256;

__device__ __forceinline__ float fast_sqrt(float x) {
    return x * rsqrtf(fmaxf(x, 1e-30f));   // x==0 -> 0, not NaN
}

struct F3 { float x, y, z; };

__device__ __forceinline__ float dist3(const F3& a, const F3& b) {
    float dx = a.x - b.x, dy = a.y - b.y, dz = a.z - b.z;
    return fast_sqrt(dx * dx + dy * dy + dz * dz);
}

__device__ __forceinline__ F3 sub3(const F3& a, const F3& b) {
    F3 r; r.x = a.x - b.x; r.y = a.y - b.y; r.z = a.z - b.z; return r;
}

__device__ __forceinline__ float cross_area(const F3& u, const F3& v) {
    float cx = u.y * v.z - u.z * v.y;
    float cy = u.z * v.x - u.x * v.z;
    float cz = u.x * v.y - u.y * v.x;
    return 0.5f * fast_sqrt(cx * cx + cy * cy + cz * cz + 1e-13f);
}

__device__ __forceinline__ void st2(float* __restrict__ p, int off, float a, float b) {
    *reinterpret_cast<float2*>(p + off) = make_float2(a, b);
}

__device__ __forceinline__ F3 loadA(const float* __restrict__ p, int jv, int iu) {
    int off = jv * ROWF + iu * 6;
    float2 ab = *reinterpret_cast<const float2*>(p + off);
    F3 r; r.x = ab.x; r.y = ab.y; r.z = p[off + 2];
    return r;
}

__device__ __forceinline__ F3 shup3(const F3& v) {
    F3 r;
    r.x = __shfl_up_sync(0xffffffffu, v.x, 1);
    r.y = __shfl_up_sync(0xffffffffu, v.y, 1);
    r.z = __shfl_up_sync(0xffffffffu, v.z, 1);
    return r;
}

__device__ __forceinline__ F3 shdn3(const F3& v) {
    F3 r;
    r.x = __shfl_down_sync(0xffffffffu, v.x, 1);
    r.y = __shfl_down_sync(0xffffffffu, v.y, 1);
    r.z = __shfl_down_sync(0xffffffffu, v.z, 1);
    return r;
}

// ---------------------------------------------------------------------------
// Pair-per-thread, warp-shuffle neighbor exchange. Thread owns nodes
// (iu even, iu+1). Lanes within a warp cover 32 consecutive pairs of one grid
// row (512 pairs/row, 32 | 512 -> warps never straddle rows). Neighbor column
// points come from shfl up/down; lanes 0/31 patch their halo via LDG.
// ---------------------------------------------------------------------------
__global__ __launch_bounds__(TPB, 6)
void k_shfl(const float* __restrict__ cand,
            const float* __restrict__ cnrm,
            float* __restrict__ out) {
    const int p    = blockIdx.x * TPB + threadIdx.x;   // pair index
    const int lane = threadIdx.x & 31;
    const int iu   = (p & 511) << 1;       // node a column (even)
    const int jv   = p >> 9;
    const int k    = jv * NU + iu;

    const bool ue   = jv > 0;
    const bool de   = jv < NV - 1;
    const bool le_a = iu > 0;
    const bool re_b = iu < NU - 2;
    const int jvU = ue ? jv - 1 : jv;
    const int jvD = de ? jv + 1 : jv;

    // --- load own pair anchors for rows U, C, D (2 LDG.128 + 1 LDG each) ---
    F3 Ua, Ub, Ca, Cb, Da, Db;
    {
        const float* bU = cand + jvU * ROWF + 6 * iu;
        const float* bC = cand + jv  * ROWF + 6 * iu;
        const float* bD = cand + jvD * ROWF + 6 * iu;
        float4 u0 = *reinterpret_cast<const float4*>(bU);
        float4 u1 = *reinterpret_cast<const float4*>(bU + 4);
        float  u2 = bU[8];
        float4 c0 = *reinterpret_cast<const float4*>(bC);
        float4 c1 = *reinterpret_cast<const float4*>(bC + 4);
        float  c2 = bC[8];
        float4 d0 = *reinterpret_cast<const float4*>(bD);
        float4 d1 = *reinterpret_cast<const float4*>(bD + 4);
        float  d2 = bD[8];
        Ua.x = u0.x; Ua.y = u0.y; Ua.z = u0.z;  Ub.x = u1.z; Ub.y = u1.w; Ub.z = u2;
        Ca.x = c0.x; Ca.y = c0.y; Ca.z = c0.z;  Cb.x = c1.z; Cb.y = c1.w; Cb.z = c2;
        Da.x = d0.x; Da.y = d0.y; Da.z = d0.z;  Db.x = d1.z; Db.y = d1.w; Db.z = d2;
    }

    // pts out immediately (shortens live ranges)
    const int p3 = OFF_PTS + 3 * k;
    st2(out, p3 + 0, Ca.x, Ca.y);
    st2(out, p3 + 2, Ca.z, Cb.x);
    st2(out, p3 + 4, Cb.y, Cb.z);

    // normals: load + store, never kept live
    {
        const float* bN = cnrm + jv * ROWF + 6 * iu;
        float4 n0 = *reinterpret_cast<const float4*>(bN);
        float4 n1 = *reinterpret_cast<const float4*>(bN + 4);
        float  n2 = bN[8];
        const int n3 = OFF_NRM + 3 * k;
        st2(out, n3 + 0, n0.x, n0.y);
        st2(out, n3 + 2, n0.z, n1.z);
        st2(out, n3 + 4, n1.w, n2);
    }

    // --- neighbor exchange via warp shuffles ---
    F3 Ul = shup3(Ub), Cl = shup3(Cb), Dl = shup3(Db);   // lane-1's b column = iu-1
    F3 Ur = shdn3(Ua), Cr = shdn3(Ca), Dr = shdn3(Da);   // lane+1's a column = iu+2
    if (lane == 0) {            // patch left halo (pair in previous warp/block)
        int iuL = max(iu - 1, 0);               // clamp; flag-guarded
        Ul = loadA(cand, jvU, iuL);
        Cl = loadA(cand, jv,  iuL);
        Dl = loadA(cand, jvD, iuL);
    }
    if (lane == 31) {           // patch right halo
        int iuR = min(iu + 2, NU - 1);          // clamp; flag-guarded
        Ur = loadA(cand, jvU, iuR);
        Cr = loadA(cand, jv,  iuR);
        Dr = loadA(cand, jvD, iuR);
    }

    // --- distances ---
    float dLa  = dist3(Ca, Cl);   // R[k-1]
    float dALa = dist3(Ca, Dl);   // A[k-1]
    float dULa = dist3(Ca, Ul);   // G[k-NU-1]
    float dRb  = dist3(Cb, Cr);   // R[k+1]
    float dGb  = dist3(Cb, Dr);   // G[k+1]
    float dAb  = dist3(Cr, Db);   // A[k+1]
    float dURb = dist3(Cb, Ur);   // A[k+1-NU]
    float dRa  = dist3(Ca, Cb);   // R[k]
    float dGa  = dist3(Ca, Db);   // G[k]
    float dDa  = dist3(Ca, Da);   // D[k]
    float dAa  = dist3(Cb, Da);   // A[k]
    float dDb  = dist3(Cb, Db);   // D[k+1]
    float dUa  = dist3(Ca, Ua);   // D[k-NU]
    float dAUa = dist3(Ca, Ub);   // A[k-NU]
    float dULb = dist3(Cb, Ua);   // G[k-NU]
    float dUb  = dist3(Cb, Ub);   // D[k+1-NU]

    // --- areas (store immediately) ---
    {
        F3 e1 = sub3(Cb, Ca), e2 = sub3(Db, Ca), f2 = sub3(Da, Ca);
        float a0a = cross_area(e1, e2);
        float a1a = cross_area(e2, f2);
        F3 g1 = sub3(Cr, Cb), g2 = sub3(Dr, Cb), h2 = sub3(Db, Cb);
        float a0b = cross_area(g1, g2);
        float a1b = cross_area(g2, h2);
        const bool rdb = re_b && de;
        st2(out, OFF_AREA + 0 * N + k, de ? a0a : 0.0f, rdb ? a0b : 0.0f);
        st2(out, OFF_AREA + 1 * N + k, de ? a1a : 0.0f, rdb ? a1b : 0.0f);
    }

    // --- radii ---
    float suma = dRa, cnta = 1.0f;
    if (de)   { suma += dGa + dDa;  cnta += 2.0f; }
    if (ue)   { suma += dUa + dAUa; cnta += 2.0f; }
    if (le_a) {
        suma += dLa; cnta += 1.0f;
        if (de) { suma += dALa; cnta += 1.0f; }
        if (ue) { suma += dULa; cnta += 1.0f; }
    }
    float sumb = dRa, cntb = 1.0f;
    if (de)   { sumb += dDb + dAa;  cntb += 2.0f; }
    if (ue)   { sumb += dULb + dUb; cntb += 2.0f; }
    if (re_b) {
        sumb += dRb; cntb += 1.0f;
        if (de) { sumb += dGb;  cntb += 1.0f; }
        if (ue) { sumb += dURb; cntb += 1.0f; }
    }
    st2(out, OFF_RAD + k, __fdividef(suma, cnta), __fdividef(sumb, cntb));

    // --- lens ---
    const bool rdb = re_b && de;
    st2(out, OFF_LEN + 0 * N + k, dRa,             re_b ? dRb : 0.0f);
    st2(out, OFF_LEN + 1 * N + k, de ? dGa : 0.0f, rdb ? dGb : 0.0f);
    st2(out, OFF_LEN + 2 * N + k, de ? dDa : 0.0f, de ? dDb : 0.0f);
    st2(out, OFF_LEN + 3 * N + k, de ? dAa : 0.0f, rdb ? dAb : 0.0f);
}

// ---------------------------------------------------------------------------
// Launch
// ---------------------------------------------------------------------------
extern "C" void kernel_launch(void* const* d_in, const int* in_sizes, int n_in,
                              void* d_out, int out_size) {
    (void)in_sizes; (void)n_in; (void)out_size;
    const float* cand = (const float*)d_in[1];
    const float* cnrm = (const float*)d_in[2];
    float* out = (float*)d_out;

    k_shfl<<<(N / 2) / TPB, TPB>>>(cand, cnrm, out);
}